// round 4
// baseline (speedup 1.0000x reference)
#include <cuda_runtime.h>
#include <cuda_bf16.h>

// Problem constants
#define BB     2
#define NN     65536
#define CC     256
#define HH     8
#define DD     64
#define SS     64
#define INNERD 512
#define TOKCH  1024   // tokens per CTA
#define TSUB   64     // token subtile

// Device scratch (no allocations allowed)
__device__ __align__(16) float g_Weff[HH][CC][SS];   // folded Wx@Wslice, [h][k][s]
__device__ __align__(16) float g_beff[HH][SS];
__device__ __align__(16) float g_acc[BB * HH * SS * DD];
__device__ __align__(16) float g_norm[BB * HH * SS];

// ---- packed f32x2 helpers (FFMA2 — only reachable via PTX) ----
__device__ __forceinline__ unsigned long long bcast2(float v) {
    unsigned long long r;
    asm("mov.b64 %0, {%1, %1};" : "=l"(r) : "f"(v));
    return r;
}
__device__ __forceinline__ void fma2(unsigned long long& d,
                                     unsigned long long a,
                                     unsigned long long b) {
    asm("fma.rn.f32x2 %0, %1, %2, %0;" : "+l"(d) : "l"(a), "l"(b));
}
__device__ __forceinline__ void unpack2(unsigned long long v, float& lo, float& hi) {
    asm("mov.b64 {%0, %1}, %2;" : "=f"(lo), "=f"(hi) : "l"(v));
}

// ---------------------------------------------------------------- zero
__global__ void zero_kernel() {
    int i = blockIdx.x * blockDim.x + threadIdx.x;
    if (i < BB * HH * SS * DD) g_acc[i] = 0.0f;
    if (i < BB * HH * SS)      g_norm[i] = 0.0f;
}

// ------------------------------------------------- precompute Weff/beff
__global__ void precompute_kernel(const float* __restrict__ Wx,
                                  const float* __restrict__ bx,
                                  const float* __restrict__ Wslice,
                                  const float* __restrict__ bslice) {
    int m = blockIdx.x;
    int s = threadIdx.x;  // 0..63
    if (m < HH * CC) {
        int h = m / CC, k = m % CC;
        float a = 0.0f;
#pragma unroll 16
        for (int d = 0; d < DD; d++)
            a += Wx[(size_t)k * INNERD + h * DD + d] * Wslice[d * SS + s];
        g_Weff[h][k][s] = a;
    } else {
        for (int h = 0; h < HH; h++) {
            float a = bslice[s];
            for (int d = 0; d < DD; d++)
                a += bx[h * DD + d] * Wslice[d * SS + s];
            g_beff[h][s] = a;
        }
    }
}

// ---------------------------------------------------------------- main
struct SmemLayout {
    float xs[64][68];     // x slab, transposed: [k][tok]  (pad 68 for banks, 16B-aligned rows)
    float we[64][64];     // Weff slab [k][s]
    float wf[64][64];     // Wfx  slab [k][d]
    float wbuf[64][68];   // softmax weights [tok][s]
    float fbuf[64][68];   // fx tile [tok][d]
    float snorm[64];
};

extern __shared__ unsigned char smem_raw[];

__global__ __launch_bounds__(256, 2) void fused_main(
    const float* __restrict__ x,
    const float* __restrict__ Wfx,
    const float* __restrict__ bfx,
    const float* __restrict__ temperature)
{
    SmemLayout& sm = *reinterpret_cast<SmemLayout*>(smem_raw);
    const int chunk = blockIdx.x;
    const int h     = blockIdx.y;
    const int b     = blockIdx.z;
    const int t  = threadIdx.x;
    const int ty = t >> 4;     // 0..15 -> token rows (GEMM1/2) / s rows (GEMM3)
    const int tx = t & 15;     // 0..15 -> s/d columns (pairs j01, j23)

    unsigned long long acc2[4][2] = {};   // packed (s, d-pair) accumulators
    float nacc[4] = {};

    float be4[4], bf4[4];
#pragma unroll
    for (int j = 0; j < 4; j++) {
        be4[j] = g_beff[h][tx * 4 + j];
        bf4[j] = bfx[h * DD + tx * 4 + j];
    }
    float tmp = temperature[h];
    tmp = fminf(fmaxf(tmp, 0.5f), 5.0f);
    const float invt = __fdividef(1.0f, tmp);

    if (t < 64) sm.snorm[t] = 0.0f;

    const size_t xbase = ((size_t)b * NN + (size_t)chunk * TOKCH) * CC;

    for (int st = 0; st < TOKCH / TSUB; st++) {
        unsigned long long proj2[4][2] = {};
        unsigned long long fxt2[4][2]  = {};
        const size_t xsub = xbase + (size_t)st * TSUB * CC;

        for (int ks = 0; ks < CC; ks += 64) {
            // ---- stage x (transposed), Weff slab, Wfx slab ----
#pragma unroll
            for (int rr = 0; rr < 4; rr++) {
                int row = ty + rr * 16;  // token row / k row
                float4 v = *reinterpret_cast<const float4*>(
                    &x[xsub + (size_t)row * CC + ks + tx * 4]);
                sm.xs[tx * 4 + 0][row] = v.x;
                sm.xs[tx * 4 + 1][row] = v.y;
                sm.xs[tx * 4 + 2][row] = v.z;
                sm.xs[tx * 4 + 3][row] = v.w;
                *reinterpret_cast<float4*>(&sm.we[row][tx * 4]) =
                    *reinterpret_cast<const float4*>(&g_Weff[h][ks + row][tx * 4]);
                *reinterpret_cast<float4*>(&sm.wf[row][tx * 4]) =
                    *reinterpret_cast<const float4*>(
                        &Wfx[(size_t)(ks + row) * INNERD + h * DD + tx * 4]);
            }
            __syncthreads();

            // ---- dual GEMM via FFMA2: proj += x@Weff, fxt += x@Wfx ----
#pragma unroll 8
            for (int k = 0; k < 64; k++) {
                float4 a = *reinterpret_cast<float4*>(&sm.xs[k][ty * 4]);
                ulonglong2 u = *reinterpret_cast<ulonglong2*>(&sm.we[k][tx * 4]);
                ulonglong2 v = *reinterpret_cast<ulonglong2*>(&sm.wf[k][tx * 4]);
                unsigned long long av[4] = {bcast2(a.x), bcast2(a.y),
                                            bcast2(a.z), bcast2(a.w)};
#pragma unroll
                for (int i = 0; i < 4; i++) {
                    fma2(proj2[i][0], av[i], u.x);
                    fma2(proj2[i][1], av[i], u.y);
                    fma2(fxt2[i][0],  av[i], v.x);
                    fma2(fxt2[i][1],  av[i], v.y);
                }
            }
            __syncthreads();
        }

        // ---- temperature-scaled softmax over s (row = token, 16 tx lanes) ----
#pragma unroll
        for (int i = 0; i < 4; i++) {
            float p[4];
            unpack2(proj2[i][0], p[0], p[1]);
            unpack2(proj2[i][1], p[2], p[3]);
#pragma unroll
            for (int j = 0; j < 4; j++) p[j] = (p[j] + be4[j]) * invt;
            float m = fmaxf(fmaxf(p[0], p[1]), fmaxf(p[2], p[3]));
#pragma unroll
            for (int off = 1; off < 16; off <<= 1)
                m = fmaxf(m, __shfl_xor_sync(0xffffffffu, m, off, 16));
            float e[4];
            float ssum = 0.0f;
#pragma unroll
            for (int j = 0; j < 4; j++) { e[j] = __expf(p[j] - m); ssum += e[j]; }
#pragma unroll
            for (int off = 1; off < 16; off <<= 1)
                ssum += __shfl_xor_sync(0xffffffffu, ssum, off, 16);
            float r = __fdividef(1.0f, ssum);
            float4 wv;
            wv.x = e[0] * r; wv.y = e[1] * r; wv.z = e[2] * r; wv.w = e[3] * r;
            nacc[0] += wv.x; nacc[1] += wv.y; nacc[2] += wv.z; nacc[3] += wv.w;
            *reinterpret_cast<float4*>(&sm.wbuf[ty * 4 + i][tx * 4]) = wv;
            float f0, f1, f2, f3;
            unpack2(fxt2[i][0], f0, f1);
            unpack2(fxt2[i][1], f2, f3);
            float4 fv;
            fv.x = f0 + bf4[0]; fv.y = f1 + bf4[1];
            fv.z = f2 + bf4[2]; fv.w = f3 + bf4[3];
            *reinterpret_cast<float4*>(&sm.fbuf[ty * 4 + i][tx * 4]) = fv;
        }
        __syncthreads();

        // ---- rank-64 update via FFMA2: acc[s][d] += w^T @ fx ----
#pragma unroll 8
        for (int kk = 0; kk < 64; kk++) {
            float4 wv = *reinterpret_cast<float4*>(&sm.wbuf[kk][ty * 4]);
            ulonglong2 fv = *reinterpret_cast<ulonglong2*>(&sm.fbuf[kk][tx * 4]);
            unsigned long long wa[4] = {bcast2(wv.x), bcast2(wv.y),
                                        bcast2(wv.z), bcast2(wv.w)};
#pragma unroll
            for (int i = 0; i < 4; i++) {
                fma2(acc2[i][0], wa[i], fv.x);
                fma2(acc2[i][1], wa[i], fv.y);
            }
        }
        __syncthreads();
    }

    // ---- per-CTA reductions -> global atomics ----
#pragma unroll
    for (int j = 0; j < 4; j++) atomicAdd(&sm.snorm[tx * 4 + j], nacc[j]);
    __syncthreads();
    if (t < 64) atomicAdd(&g_norm[(b * HH + h) * SS + t], sm.snorm[t]);

    const int obase = ((b * HH + h) * SS + ty * 4) * DD + tx * 4;
#pragma unroll
    for (int i = 0; i < 4; i++) {
        float a0, a1, a2, a3;
        unpack2(acc2[i][0], a0, a1);
        unpack2(acc2[i][1], a2, a3);
        atomicAdd(&g_acc[obase + i * DD + 0], a0);
        atomicAdd(&g_acc[obase + i * DD + 1], a1);
        atomicAdd(&g_acc[obase + i * DD + 2], a2);
        atomicAdd(&g_acc[obase + i * DD + 3], a3);
    }
}

// ------------------------------------------------------------ finalize
__global__ void finalize_kernel(float* __restrict__ out) {
    int i = blockIdx.x * blockDim.x + threadIdx.x;
    if (i < BB * HH * SS * DD)
        out[i] = g_acc[i] / (g_norm[i >> 6] + 0.01f);
}

// -------------------------------------------------------------- launch
extern "C" void kernel_launch(void* const* d_in, const int* in_sizes, int n_in,
                              void* d_out, int out_size) {
    const float* x           = (const float*)d_in[0];
    const float* Wfx         = (const float*)d_in[3];
    const float* bfx         = (const float*)d_in[4];
    const float* Wx          = (const float*)d_in[1];
    const float* bx          = (const float*)d_in[2];
    const float* Wslice      = (const float*)d_in[5];
    const float* bslice      = (const float*)d_in[6];
    const float* temperature = (const float*)d_in[7];
    float* out = (float*)d_out;

    cudaFuncSetAttribute(fused_main, cudaFuncAttributeMaxDynamicSharedMemorySize,
                         (int)sizeof(SmemLayout));

    zero_kernel<<<(BB * HH * SS * DD + 255) / 256, 256>>>();
    precompute_kernel<<<HH * CC + 1, 64>>>(Wx, bx, Wslice, bslice);
    fused_main<<<dim3(NN / TOKCH, HH, BB), 256, sizeof(SmemLayout)>>>(
        x, Wfx, bfx, temperature);
    finalize_kernel<<<(BB * HH * SS * DD + 255) / 256, 256>>>(out);
}

// round 7
// speedup vs baseline: 2.1751x; 2.1751x over previous
#include <cuda_runtime.h>
#include <cuda_bf16.h>
#include <cstdint>

// Problem constants
#define BB 2
#define NN 65536
#define CC 256
#define HH 8
#define DD 64
#define SS 64
#define INNERD 512
#define NTOK (BB * NN)      // 131072
#define NCTA (NTOK / 128)   // 1024

// smem layout (bytes); rows padded to 272B (136 bf16) for conflict-free ldmatrix
#define OFF_BS   0
#define OFF_BD   256
#define OFF_A    1024
#define ABUF     34816                   // 128 rows * 272B
#define OFF_B    (OFF_A + 4 * ABUF)      // 140288
#define BBUF     34816
#define OFF_WH   OFF_B                   // w hi   64*272 = 17408
#define OFF_WL   (OFF_B + 17408)
#define OFF_FH   (OFF_B + BBUF)          // f hi
#define OFF_FL   (OFF_FH + 17408)
#define SMEM_TOTAL (OFF_B + 2 * BBUF)    // 209920

// Device scratch (static, no allocations)
__device__ __align__(16) float g_Weff[HH][CC][SS];
__device__ __align__(16) float g_beff[HH][SS];
__device__ __align__(16) float g_acc[BB * HH * SS * DD];
__device__ __align__(16) float g_norm[BB * HH * SS];
__device__ __align__(16) unsigned short g_Axh[(size_t)NTOK * CC];
__device__ __align__(16) unsigned short g_Axl[(size_t)NTOK * CC];
__device__ __align__(16) unsigned short g_Bth[HH * 128 * CC];
__device__ __align__(16) unsigned short g_Btl[HH * 128 * CC];

// ---------------- helpers ----------------
__device__ __forceinline__ uint32_t smem_u32(const void* p) {
    uint32_t a;
    asm("{ .reg .u64 t; cvta.to.shared.u64 t, %1; cvt.u32.u64 %0, t; }" : "=r"(a) : "l"(p));
    return a;
}
__device__ __forceinline__ void ldsm4(uint32_t* r, uint32_t addr) {
    asm volatile("ldmatrix.sync.aligned.m8n8.x4.shared.b16 {%0,%1,%2,%3}, [%4];"
                 : "=r"(r[0]), "=r"(r[1]), "=r"(r[2]), "=r"(r[3]) : "r"(addr));
}
__device__ __forceinline__ void mma16816(float* c, const uint32_t* a,
                                         uint32_t b0, uint32_t b1) {
    asm volatile(
        "mma.sync.aligned.m16n8k16.row.col.f32.bf16.bf16.f32 "
        "{%0,%1,%2,%3}, {%4,%5,%6,%7}, {%8,%9}, {%0,%1,%2,%3};"
        : "+f"(c[0]), "+f"(c[1]), "+f"(c[2]), "+f"(c[3])
        : "r"(a[0]), "r"(a[1]), "r"(a[2]), "r"(a[3]), "r"(b0), "r"(b1));
}
__device__ __forceinline__ void split1(float v, unsigned short& hi, unsigned short& lo) {
    __nv_bfloat16 h = __float2bfloat16(v);
    __nv_bfloat16 l = __float2bfloat16(v - __bfloat162float(h));
    hi = __bfloat16_as_ushort(h);
    lo = __bfloat16_as_ushort(l);
}

// ---------------------------------------------------------------- zero
__global__ void zero_kernel() {
    int i = blockIdx.x * blockDim.x + threadIdx.x;
    if (i < BB * HH * SS * DD) g_acc[i] = 0.0f;
    if (i < BB * HH * SS)      g_norm[i] = 0.0f;
}

// ------------------------------------------------- precompute Weff/beff
__global__ void precompute_kernel(const float* __restrict__ Wx,
                                  const float* __restrict__ bx,
                                  const float* __restrict__ Wslice,
                                  const float* __restrict__ bslice) {
    int m = blockIdx.x;
    int s = threadIdx.x;
    if (m < HH * CC) {
        int h = m / CC, k = m % CC;
        float a = 0.0f;
#pragma unroll 16
        for (int d = 0; d < DD; d++)
            a += Wx[(size_t)k * INNERD + h * DD + d] * Wslice[d * SS + s];
        g_Weff[h][k][s] = a;
    } else {
        for (int h = 0; h < HH; h++) {
            float a = bslice[s];
            for (int d = 0; d < DD; d++)
                a += bx[h * DD + d] * Wslice[d * SS + s];
            g_beff[h][s] = a;
        }
    }
}

// ---------------- B^T images: [h][n(64 s | 64 d)][K=256] bf16 hi/lo
__global__ void build_bt(const float* __restrict__ Wfx) {
    int h = blockIdx.x;
    for (int i = threadIdx.x; i < 128 * 256; i += 256) {
        int n = i >> 8, K = i & 255;
        float v = (n < 64) ? g_Weff[h][K][n]
                           : Wfx[(size_t)K * INNERD + h * DD + (n - 64)];
        unsigned short hi, lo;
        split1(v, hi, lo);
        g_Bth[(h * 128 + n) * 256 + K] = hi;
        g_Btl[(h * 128 + n) * 256 + K] = lo;
    }
}

// ---------------- x -> bf16 hi/lo images, row-major [tok][256]
__global__ void convert_x(const float* __restrict__ x) {
    size_t base = (size_t)blockIdx.x * 32768;  // 128 tok * 256
    for (int i = threadIdx.x; i < 8192; i += 256) {
        float4 v = *(const float4*)&x[base + (size_t)i * 4];
        ushort4 h, l;
        split1(v.x, h.x, l.x); split1(v.y, h.y, l.y);
        split1(v.z, h.z, l.z); split1(v.w, h.w, l.w);
        *(ushort4*)&g_Axh[base + (size_t)i * 4] = h;
        *(ushort4*)&g_Axl[base + (size_t)i * 4] = l;
    }
}

// ---------------------------------------------------------------- main
extern __shared__ unsigned char smem[];

__global__ __launch_bounds__(256, 1) void fused_main(
    const float* __restrict__ bfx,
    const float* __restrict__ temperature)
{
    const uint32_t smb = smem_u32(smem);
    const int ct   = blockIdx.x;
    const int t    = threadIdx.x;
    const int wp   = t >> 5;
    const int lane = t & 31;
    const int g    = lane >> 2;
    const int q    = lane & 3;
    const int tok0 = ct * 128;
    const int b    = ct >> 9;

    // ldmatrix lane-address components (x4 fragment convention)
    const uint32_t a_row = (lane & 7) + ((lane >> 3) & 1) * 8;  // within m16
    const uint32_t a_k8  = (lane >> 4) * 8;
    const uint32_t b_row = (lane & 7) + (lane >> 4) * 8;        // within n16
    const uint32_t b_k8  = ((lane >> 3) & 1) * 8;

    // ---- stage A (both K-halves, hi+lo) once ----
#pragma unroll
    for (int kh = 0; kh < 2; kh++)
#pragma unroll
        for (int sp = 0; sp < 2; sp++) {
            const unsigned short* src = sp ? g_Axl : g_Axh;
            unsigned char* dst = smem + OFF_A + (kh * 2 + sp) * ABUF;
            for (int i = t; i < 2048; i += 256) {
                int row = i >> 4, u = i & 15;
                uint4 v = *(const uint4*)&src[(size_t)(tok0 + row) * CC + kh * 128 + u * 8];
                *(uint4*)(dst + row * 272 + u * 16) = v;
            }
        }

    float nacc[16];

    for (int h = 0; h < HH; h++) {
        if (t < 64) {
            ((float*)(smem + OFF_BS))[t] = g_beff[h][t];
            ((float*)(smem + OFF_BD))[t] = bfx[h * DD + t];
        }
        float tmp = temperature[h];
        tmp = fminf(fmaxf(tmp, 0.5f), 5.0f);
        const float invt = __fdividef(1.0f, tmp);

        float c[16][4];
#pragma unroll
        for (int i = 0; i < 16; i++)
#pragma unroll
            for (int j = 0; j < 4; j++) c[i][j] = 0.0f;
#pragma unroll
        for (int i = 0; i < 16; i++) nacc[i] = 0.0f;

        // ================= GEMM1: [128 tok x 256] @ [256 x 128 N] =================
        for (int kh = 0; kh < 2; kh++) {
            __syncthreads();   // prior readers of B/wf region done
            // stage B half (hi+lo)
#pragma unroll
            for (int sp = 0; sp < 2; sp++) {
                const unsigned short* src = sp ? g_Btl : g_Bth;
                unsigned char* dst = smem + OFF_B + sp * BBUF;
                for (int i = t; i < 2048; i += 256) {
                    int row = i >> 4, u = i & 15;
                    uint4 v = *(const uint4*)&src[(size_t)(h * 128 + row) * CC + kh * 128 + u * 8];
                    *(uint4*)(dst + row * 272 + u * 16) = v;
                }
            }
            __syncthreads();

            const uint32_t Ah = smb + OFF_A + (kh * 2 + 0) * ABUF;
            const uint32_t Al = Ah + ABUF;
            const uint32_t Bh = smb + OFF_B;
            const uint32_t Bl = Bh + BBUF;
            const uint32_t arow_off = (wp * 16 + a_row) * 272;

#pragma unroll
            for (int ks = 0; ks < 8; ks++) {
                uint32_t ak = (ks * 16 + a_k8) * 2;
                uint32_t bk = (ks * 16 + b_k8) * 2;
                uint32_t ah[4], al[4];
                ldsm4(ah, Ah + arow_off + ak);
                ldsm4(al, Al + arow_off + ak);
#pragma unroll
                for (int hg = 0; hg < 2; hg++) {
                    uint32_t bh[16], bl[16];
#pragma unroll
                    for (int np = 0; np < 4; np++) {
                        uint32_t ro = (hg * 64 + np * 16 + b_row) * 272 + bk;
                        ldsm4(&bh[np * 4], Bh + ro);
                        ldsm4(&bl[np * 4], Bl + ro);
                    }
#pragma unroll
                    for (int nt = 0; nt < 8; nt++)
                        mma16816(c[hg * 8 + nt], ah, bh[nt * 2], bh[nt * 2 + 1]);
#pragma unroll
                    for (int nt = 0; nt < 8; nt++)
                        mma16816(c[hg * 8 + nt], ah, bl[nt * 2], bl[nt * 2 + 1]);
#pragma unroll
                    for (int nt = 0; nt < 8; nt++)
                        mma16816(c[hg * 8 + nt], al, bh[nt * 2], bh[nt * 2 + 1]);
                }
            }
        }
        __syncthreads();   // all warps done reading B -> wf region reusable

        // ================= softmax + transposed split stores =================
        {
            const float* bsn = (const float*)(smem + OFF_BS);
            const float* bdn = (const float*)(smem + OFF_BD);
            unsigned short* whp = (unsigned short*)(smem + OFF_WH);
            unsigned short* wlp = (unsigned short*)(smem + OFF_WL);
            unsigned short* fhp = (unsigned short*)(smem + OFF_FH);
            unsigned short* flp = (unsigned short*)(smem + OFF_FL);
#pragma unroll
            for (int rr = 0; rr < 2; rr++) {
                const int tokg = wp * 16 + g + rr * 8;
                float pv[16];
                float mx = -1e30f;
#pragma unroll
                for (int nt = 0; nt < 8; nt++)
#pragma unroll
                    for (int e = 0; e < 2; e++) {
                        float p = (c[nt][rr * 2 + e] + bsn[nt * 8 + q * 2 + e]) * invt;
                        pv[nt * 2 + e] = p;
                        mx = fmaxf(mx, p);
                    }
                mx = fmaxf(mx, __shfl_xor_sync(0xffffffffu, mx, 1));
                mx = fmaxf(mx, __shfl_xor_sync(0xffffffffu, mx, 2));
                float sv = 0.0f;
#pragma unroll
                for (int j = 0; j < 16; j++) { pv[j] = __expf(pv[j] - mx); sv += pv[j]; }
                sv += __shfl_xor_sync(0xffffffffu, sv, 1);
                sv += __shfl_xor_sync(0xffffffffu, sv, 2);
                const float r = __fdividef(1.0f, sv);
#pragma unroll
                for (int nt = 0; nt < 8; nt++)
#pragma unroll
                    for (int e = 0; e < 2; e++) {
                        float wv = pv[nt * 2 + e] * r;
                        nacc[nt * 2 + e] += wv;
                        unsigned short hi, lo;
                        split1(wv, hi, lo);
                        int idx = (nt * 8 + q * 2 + e) * 136 + tokg;
                        whp[idx] = hi; wlp[idx] = lo;
                    }
#pragma unroll
                for (int nt = 0; nt < 8; nt++)
#pragma unroll
                    for (int e = 0; e < 2; e++) {
                        float fv = c[8 + nt][rr * 2 + e] + bdn[nt * 8 + q * 2 + e];
                        unsigned short hi, lo;
                        split1(fv, hi, lo);
                        int idx = (nt * 8 + q * 2 + e) * 136 + tokg;
                        fhp[idx] = hi; flp[idx] = lo;
                    }
            }
        }
        __syncthreads();

        // ================= rank update: acc[s][d] += w^T @ fx =================
        {
            const uint32_t Wh = smb + OFF_WH, Wl = smb + OFF_WL;
            const uint32_t Fh = smb + OFF_FH, Fl = smb + OFF_FL;
            const int m0r = (wp & 3) * 16;
            const int n0r = (wp >> 2) * 32;
            float racc[4][4];
#pragma unroll
            for (int i = 0; i < 4; i++)
#pragma unroll
                for (int j = 0; j < 4; j++) racc[i][j] = 0.0f;

#pragma unroll
            for (int ks = 0; ks < 8; ks++) {
                uint32_t ak = (ks * 16 + a_k8) * 2;
                uint32_t bk = (ks * 16 + b_k8) * 2;
                uint32_t ah[4], al[4], bh[8], bl[8];
                ldsm4(ah, Wh + (m0r + a_row) * 272 + ak);
                ldsm4(al, Wl + (m0r + a_row) * 272 + ak);
#pragma unroll
                for (int np = 0; np < 2; np++) {
                    uint32_t ro = (n0r + np * 16 + b_row) * 272 + bk;
                    ldsm4(&bh[np * 4], Fh + ro);
                    ldsm4(&bl[np * 4], Fl + ro);
                }
#pragma unroll
                for (int nt = 0; nt < 4; nt++) mma16816(racc[nt], ah, bh[nt * 2], bh[nt * 2 + 1]);
#pragma unroll
                for (int nt = 0; nt < 4; nt++) mma16816(racc[nt], ah, bl[nt * 2], bl[nt * 2 + 1]);
#pragma unroll
                for (int nt = 0; nt < 4; nt++) mma16816(racc[nt], al, bh[nt * 2], bh[nt * 2 + 1]);
            }

            // rank atomics (note: racc rows = s, cols = d)
            const int abase = (b * HH + h) * SS;
#pragma unroll
            for (int nt = 0; nt < 4; nt++)
#pragma unroll
                for (int rr = 0; rr < 2; rr++)
#pragma unroll
                    for (int e = 0; e < 2; e++) {
                        int s = m0r + g + rr * 8;
                        int d = n0r + nt * 8 + q * 2 + e;
                        atomicAdd(&g_acc[(abase + s) * DD + d], racc[nt][rr * 2 + e]);
                    }
        }

        // ---- norm reduce + atomics ----
#pragma unroll
        for (int j = 0; j < 16; j++) {
            nacc[j] += __shfl_xor_sync(0xffffffffu, nacc[j], 4);
            nacc[j] += __shfl_xor_sync(0xffffffffu, nacc[j], 8);
            nacc[j] += __shfl_xor_sync(0xffffffffu, nacc[j], 16);
        }
        if (g == 0) {
            const int nb = (b * HH + h) * SS;
#pragma unroll
            for (int nt = 0; nt < 8; nt++)
#pragma unroll
                for (int e = 0; e < 2; e++)
                    atomicAdd(&g_norm[nb + nt * 8 + q * 2 + e], nacc[nt * 2 + e]);
        }
    }
}

// ------------------------------------------------------------ finalize
__global__ void finalize_kernel(float* __restrict__ out) {
    int i = blockIdx.x * blockDim.x + threadIdx.x;
    if (i < BB * HH * SS * DD)
        out[i] = g_acc[i] / (g_norm[i >> 6] + 0.01f);
}

// -------------------------------------------------------------- launch
extern "C" void kernel_launch(void* const* d_in, const int* in_sizes, int n_in,
                              void* d_out, int out_size) {
    const float* x           = (const float*)d_in[0];
    const float* Wx          = (const float*)d_in[1];
    const float* bx          = (const float*)d_in[2];
    const float* Wfx         = (const float*)d_in[3];
    const float* bfx         = (const float*)d_in[4];
    const float* Wslice      = (const float*)d_in[5];
    const float* bslice      = (const float*)d_in[6];
    const float* temperature = (const float*)d_in[7];
    float* out = (float*)d_out;

    cudaFuncSetAttribute(fused_main, cudaFuncAttributeMaxDynamicSharedMemorySize,
                         SMEM_TOTAL);

    zero_kernel<<<(BB * HH * SS * DD + 255) / 256, 256>>>();
    precompute_kernel<<<HH * CC + 1, 64>>>(Wx, bx, Wslice, bslice);
    build_bt<<<HH, 256>>>(Wfx);
    convert_x<<<NCTA, 256>>>(x);
    fused_main<<<NCTA, 256, SMEM_TOTAL>>>(bfx, temperature);
    finalize_kernel<<<(BB * HH * SS * DD + 255) / 256, 256>>>(out);
}

// round 8
// speedup vs baseline: 2.9767x; 1.3685x over previous
#include <cuda_runtime.h>
#include <cuda_bf16.h>
#include <cstdint>

// Problem constants
#define BB 2
#define NN 65536
#define CC 256
#define HH 8
#define DD 64
#define SS 64
#define INNERD 512
#define NTOK (BB * NN)      // 131072
#define NCTA (NTOK / 128)   // 1024

// smem layout (floats/bytes). Row strides chosen ≡ 4 (mod 32) words -> conflict-free
#define AST 260                          // A row stride (floats): 256 + 4
#define BST 132                          // B/w/f row stride (floats): 128 + 4
#define OFF_BS 0
#define OFF_BD 256
#define OFF_A  1024
#define OFF_B  (OFF_A + 128 * AST * 4)   // 135168
#define OFF_W  OFF_B                     // w aliases B region (64 rows)
#define OFF_F  (OFF_B + 64 * BST * 4)    // f aliases B region (64 rows)
#define SMEM_TOTAL (OFF_B + 128 * BST * 4)  // 202752

// Device scratch (static, no allocations)
__device__ __align__(16) float g_Weff[HH][CC][SS];
__device__ __align__(16) float g_beff[HH][SS];
__device__ __align__(16) float g_acc[BB * HH * SS * DD];
__device__ __align__(16) float g_norm[BB * HH * SS];
__device__ __align__(16) float g_Btf[HH * 128 * CC];   // tf32-rounded B^T images

// ---------------- helpers ----------------
__device__ __forceinline__ uint32_t cvt_tf32(float v) {
    uint32_t r;
    asm("cvt.rna.tf32.f32 %0, %1;" : "=r"(r) : "f"(v));
    return r;
}
__device__ __forceinline__ void mma_tf32(float* c, const uint32_t* a,
                                         uint32_t b0, uint32_t b1) {
    asm volatile(
        "mma.sync.aligned.m16n8k8.row.col.f32.tf32.tf32.f32 "
        "{%0,%1,%2,%3}, {%4,%5,%6,%7}, {%8,%9}, {%0,%1,%2,%3};"
        : "+f"(c[0]), "+f"(c[1]), "+f"(c[2]), "+f"(c[3])
        : "r"(a[0]), "r"(a[1]), "r"(a[2]), "r"(a[3]), "r"(b0), "r"(b1));
}

// ---------------------------------------------------------------- zero
__global__ void zero_kernel() {
    int i = blockIdx.x * blockDim.x + threadIdx.x;
    if (i < BB * HH * SS * DD) g_acc[i] = 0.0f;
    if (i < BB * HH * SS)      g_norm[i] = 0.0f;
}

// ------------------------------------------------- precompute Weff/beff
__global__ void precompute_kernel(const float* __restrict__ Wx,
                                  const float* __restrict__ bx,
                                  const float* __restrict__ Wslice,
                                  const float* __restrict__ bslice) {
    int m = blockIdx.x;
    int s = threadIdx.x;
    if (m < HH * CC) {
        int h = m / CC, k = m % CC;
        float a = 0.0f;
#pragma unroll 16
        for (int d = 0; d < DD; d++)
            a += Wx[(size_t)k * INNERD + h * DD + d] * Wslice[d * SS + s];
        g_Weff[h][k][s] = a;
    } else {
        for (int h = 0; h < HH; h++) {
            float a = bslice[s];
            for (int d = 0; d < DD; d++)
                a += bx[h * DD + d] * Wslice[d * SS + s];
            g_beff[h][s] = a;
        }
    }
}

// ---------------- B^T images: [h][n(64 s | 64 d)][K=256], tf32-rounded fp32
__global__ void build_bt(const float* __restrict__ Wfx) {
    int h = blockIdx.x;
    for (int i = threadIdx.x; i < 128 * 256; i += 256) {
        int n = i >> 8, K = i & 255;
        float v = (n < 64) ? g_Weff[h][K][n]
                           : Wfx[(size_t)K * INNERD + h * DD + (n - 64)];
        g_Btf[(size_t)(h * 128 + n) * 256 + K] = __uint_as_float(cvt_tf32(v));
    }
}

// ---------------------------------------------------------------- main
extern __shared__ unsigned char smem[];

__global__ __launch_bounds__(256, 1) void fused_main(
    const float* __restrict__ x,
    const float* __restrict__ bfx,
    const float* __restrict__ temperature)
{
    const int ct   = blockIdx.x;
    const int t    = threadIdx.x;
    const int wp   = t >> 5;
    const int lane = t & 31;
    const int g    = lane >> 2;       // 0..7
    const int q    = lane & 3;        // 0..3
    const int wm   = wp & 3;          // GEMM1 m-group (32 tok)
    const int wn   = wp >> 2;         // GEMM1 n-group (0: s-half, 1: d-half)
    const int tok0 = ct * 128;
    const int b    = ct >> 9;

    float*    smf = (float*)smem;
    uint32_t* smu = (uint32_t*)smem;
    const int A0 = OFF_A / 4, B0 = OFF_B / 4, W0 = OFF_W / 4, F0 = OFF_F / 4;

    // ---- stage A once: x -> tf32-rounded, rows padded to AST ----
    for (int it = 0; it < 32; it++) {
        int idx = it * 256 + t;             // float4 index over 128x64
        int row = idx >> 6, c4 = idx & 63;
        float4 v = *(const float4*)&x[((size_t)(tok0 + row)) * CC + c4 * 4];
        uint32_t* d = &smu[A0 + row * AST + c4 * 4];
        d[0] = cvt_tf32(v.x); d[1] = cvt_tf32(v.y);
        d[2] = cvt_tf32(v.z); d[3] = cvt_tf32(v.w);
    }

    for (int h = 0; h < HH; h++) {
        float tmp = temperature[h];
        tmp = fminf(fmaxf(tmp, 0.5f), 5.0f);
        const float invt = __fdividef(1.0f, tmp);

        float c[2][8][4];
#pragma unroll
        for (int i = 0; i < 2; i++)
#pragma unroll
            for (int j = 0; j < 8; j++)
#pragma unroll
                for (int e = 0; e < 4; e++) c[i][j][e] = 0.0f;

        // ============ GEMM1: [128 tok x 256] @ [256 x 128 (s|d)] ============
        for (int kh = 0; kh < 2; kh++) {
            __syncthreads();  // prior readers of B/w/f region done
            // stage B half [128 n][128 k] (already tf32-rounded in gmem)
            const float* src = g_Btf + (size_t)h * 128 * 256 + kh * 128;
            for (int it = 0; it < 16; it++) {
                int idx = it * 256 + t;       // float4 over 128x32
                int row = idx >> 5, c4 = idx & 31;
                float4 v = *(const float4*)&src[(size_t)row * 256 + c4 * 4];
                *(float4*)&smf[B0 + row * BST + c4 * 4] = v;
            }
            if (kh == 0 && t < 64) {
                smf[OFF_BS / 4 + t] = g_beff[h][t];
                smf[OFF_BD / 4 + t] = bfx[h * DD + t];
            }
            __syncthreads();

#pragma unroll 4
            for (int ks = 0; ks < 16; ks++) {
                const int kc = kh * 128 + ks * 8;
                uint32_t a[2][4];
#pragma unroll
                for (int mt = 0; mt < 2; mt++) {
                    const int r0 = wm * 32 + mt * 16 + g;
                    const uint32_t* p0 = &smu[A0 + r0 * AST + kc + q];
                    const uint32_t* p1 = &smu[A0 + (r0 + 8) * AST + kc + q];
                    a[mt][0] = p0[0]; a[mt][2] = p0[4];
                    a[mt][1] = p1[0]; a[mt][3] = p1[4];
                }
#pragma unroll
                for (int nt = 0; nt < 8; nt++) {
                    const uint32_t* bp =
                        &smu[B0 + (wn * 64 + nt * 8 + g) * BST + ks * 8 + q];
                    uint32_t b0 = bp[0], b1 = bp[4];
                    mma_tf32(c[0][nt], a[0], b0, b1);
                    mma_tf32(c[1][nt], a[1], b0, b1);
                }
            }
        }
        __syncthreads();  // B reads done -> w/f region writable

        // ============ softmax (s-half warps) / f-store (d-half warps) ============
        float nacc[16];
#pragma unroll
        for (int i = 0; i < 16; i++) nacc[i] = 0.0f;

        if (wn == 0) {
            const float* bs = &smf[OFF_BS / 4];
#pragma unroll
            for (int mt = 0; mt < 2; mt++)
#pragma unroll
                for (int rr = 0; rr < 2; rr++) {
                    const int tok = wm * 32 + mt * 16 + g + 8 * rr;
                    float pv[16];
                    float mx = -1e30f;
#pragma unroll
                    for (int nt = 0; nt < 8; nt++)
#pragma unroll
                        for (int e = 0; e < 2; e++) {
                            float p = (c[mt][nt][rr * 2 + e] + bs[nt * 8 + 2 * q + e]) * invt;
                            pv[nt * 2 + e] = p;
                            mx = fmaxf(mx, p);
                        }
                    mx = fmaxf(mx, __shfl_xor_sync(0xffffffffu, mx, 1));
                    mx = fmaxf(mx, __shfl_xor_sync(0xffffffffu, mx, 2));
                    float sv = 0.0f;
#pragma unroll
                    for (int j = 0; j < 16; j++) { pv[j] = __expf(pv[j] - mx); sv += pv[j]; }
                    sv += __shfl_xor_sync(0xffffffffu, sv, 1);
                    sv += __shfl_xor_sync(0xffffffffu, sv, 2);
                    const float r = __fdividef(1.0f, sv);
#pragma unroll
                    for (int nt = 0; nt < 8; nt++)
#pragma unroll
                        for (int e = 0; e < 2; e++) {
                            float wv = pv[nt * 2 + e] * r;
                            nacc[nt * 2 + e] += wv;
                            smu[W0 + (nt * 8 + 2 * q + e) * BST + tok] = cvt_tf32(wv);
                        }
                }
        } else {
            const float* bd = &smf[OFF_BD / 4];
#pragma unroll
            for (int mt = 0; mt < 2; mt++)
#pragma unroll
                for (int rr = 0; rr < 2; rr++) {
                    const int tok = wm * 32 + mt * 16 + g + 8 * rr;
#pragma unroll
                    for (int nt = 0; nt < 8; nt++)
#pragma unroll
                        for (int e = 0; e < 2; e++) {
                            float fv = c[mt][nt][rr * 2 + e] + bd[nt * 8 + 2 * q + e];
                            smu[F0 + (nt * 8 + 2 * q + e) * BST + tok] = cvt_tf32(fv);
                        }
                }
        }
        __syncthreads();

        // ============ rank update: acc[64 s][64 d] += w^T @ fx, K=128 tok ============
        {
            const int wm2 = wp & 3;    // s-tile (16)
            const int wn2 = wp >> 2;   // d-group (32)
            float racc[4][4];
#pragma unroll
            for (int i = 0; i < 4; i++)
#pragma unroll
                for (int j = 0; j < 4; j++) racc[i][j] = 0.0f;

#pragma unroll 4
            for (int ks = 0; ks < 16; ks++) {
                uint32_t a[4];
                const int r0 = wm2 * 16 + g;
                const uint32_t* p0 = &smu[W0 + r0 * BST + ks * 8 + q];
                const uint32_t* p1 = &smu[W0 + (r0 + 8) * BST + ks * 8 + q];
                a[0] = p0[0]; a[2] = p0[4];
                a[1] = p1[0]; a[3] = p1[4];
#pragma unroll
                for (int nt = 0; nt < 4; nt++) {
                    const uint32_t* bp =
                        &smu[F0 + (wn2 * 32 + nt * 8 + g) * BST + ks * 8 + q];
                    mma_tf32(racc[nt], a, bp[0], bp[4]);
                }
            }

            const int abase = (b * HH + h) * SS;
#pragma unroll
            for (int nt = 0; nt < 4; nt++)
#pragma unroll
                for (int rr = 0; rr < 2; rr++)
#pragma unroll
                    for (int e = 0; e < 2; e++) {
                        int s = wm2 * 16 + g + 8 * rr;
                        int d = wn2 * 32 + nt * 8 + 2 * q + e;
                        atomicAdd(&g_acc[(abase + s) * DD + d], racc[nt][rr * 2 + e]);
                    }
        }

        // ---- norm reduce + atomics (s-half warps only) ----
        if (wn == 0) {
#pragma unroll
            for (int j = 0; j < 16; j++) {
                nacc[j] += __shfl_xor_sync(0xffffffffu, nacc[j], 4);
                nacc[j] += __shfl_xor_sync(0xffffffffu, nacc[j], 8);
                nacc[j] += __shfl_xor_sync(0xffffffffu, nacc[j], 16);
            }
            if (g == 0) {
                const int nb = (b * HH + h) * SS;
#pragma unroll
                for (int nt = 0; nt < 8; nt++)
#pragma unroll
                    for (int e = 0; e < 2; e++)
                        atomicAdd(&g_norm[nb + nt * 8 + 2 * q + e], nacc[nt * 2 + e]);
            }
        }
    }
}

// ------------------------------------------------------------ finalize
__global__ void finalize_kernel(float* __restrict__ out) {
    int i = blockIdx.x * blockDim.x + threadIdx.x;
    if (i < BB * HH * SS * DD)
        out[i] = g_acc[i] / (g_norm[i >> 6] + 0.01f);
}

// -------------------------------------------------------------- launch
extern "C" void kernel_launch(void* const* d_in, const int* in_sizes, int n_in,
                              void* d_out, int out_size) {
    const float* x           = (const float*)d_in[0];
    const float* Wx          = (const float*)d_in[1];
    const float* bx          = (const float*)d_in[2];
    const float* Wfx         = (const float*)d_in[3];
    const float* bfx         = (const float*)d_in[4];
    const float* Wslice      = (const float*)d_in[5];
    const float* bslice      = (const float*)d_in[6];
    const float* temperature = (const float*)d_in[7];
    float* out = (float*)d_out;

    cudaFuncSetAttribute(fused_main, cudaFuncAttributeMaxDynamicSharedMemorySize,
                         SMEM_TOTAL);

    zero_kernel<<<(BB * HH * SS * DD + 255) / 256, 256>>>();
    precompute_kernel<<<HH * CC + 1, 64>>>(Wx, bx, Wslice, bslice);
    build_bt<<<HH, 256>>>(Wfx);
    fused_main<<<NCTA, 256, SMEM_TOTAL>>>(x, bfx, temperature);
    finalize_kernel<<<(BB * HH * SS * DD + 255) / 256, 256>>>(out);
}